// round 15
// speedup vs baseline: 4.2200x; 1.0224x over previous
#include <cuda_runtime.h>
#include <cuda_fp16.h>
#include <cooperative_groups.h>
#include <math.h>
#include <stdint.h>

namespace cg = cooperative_groups;

// ---------------- problem constants ----------------
constexpr int Bb   = 4;
constexpr int NIN  = 6170;
constexpr int Lf   = 768;
constexpr int Dd   = 512;
constexpr int NT   = 6264;
constexpr int NP   = 6400;
constexpr int PADT = 136;
constexpr int HH   = 8;
constexpr int DH   = 64;
constexpr int LM   = 256;
constexpr int LFAC = 25;
constexpr long long QSZ = (long long)Bb*HH*NP*DH;

// ---------------- device scratch ----------------
__device__ float  g_H  [12828672];
__device__ float  g_H2 [12828672];
__device__ __half g_XR [18954240];
__device__ __half g_WT [2490368];
__device__ __half g_XP [13107200];
__device__ __half g_QKV[39321600];
__device__ __half g_QL [524288];
__device__ __half g_KL [524288];
__device__ __half g_A2 [2097152];
__device__ __half g_AZa[2097152];
__device__ __half g_T1a[2097152];
__device__ __half g_AZb[2097152];
__device__ __half g_T1b[2097152];
__device__ __half g_T2 [2097152];
__device__ __half g_T3 [2097152];
__device__ __half g_Za [2097152];
__device__ __half g_Zb [2097152];
__device__ float  g_RED[64];
__device__ float  g_SSUM[8192];
__device__ float  g_A3VF[524288];
__device__ __half g_A3V[524288];
__device__ __half g_W2 [524288];     // W2 transposed: [bh][d=64][l=256]
__device__ __half g_ATT[13107200];

constexpr int W_FC1 = 0;
constexpr int W_Q1  = 393216;
constexpr int W_Q2  = 1179648;
constexpr int W_O1  = 1966080;
constexpr int W_O2  = 2228224;

// ---------------- GEMM params ----------------
struct GP {
  const __half* A; long long sA; int lda;
  const __half* B; long long sB; int ldb;
  void*         C; long long sC; int ldc;
  int M, N, K, ksplit, epi;
  const float* bias; float alpha; void* out2;
};
// epi: 0 half C   2 qkv scatter   6 f32 residual+=   9 f32 C
//      12 relu+bias -> token-scattered H   13 half transposed out2[gn][gm]

__device__ __forceinline__ void epi2_store(const GP& p, int z, int gm, int gn,
                                           float v0, float v1){
  switch(p.epi){
    case 0:
      *(__half2*)((__half*)p.C + (long long)z*p.sC + (long long)gm*p.ldc + gn)
          = __floats2half2_rn(v0, v1);
      break;
    case 2: {
      int which = gn >> 9; int hh = (gn >> 6) & 7; int d = gn & 63;
      float s = (which==0) ? p.alpha : 1.f;
      long long off = (long long)which*QSZ + (((long long)z*HH+hh)*NP + gm)*DH + d;
      *(__half2*)((__half*)p.out2 + off) = __floats2half2_rn(s*v0, s*v1);
    } break;
    case 6: {
      float* c = (float*)p.C + (long long)z*p.sC + (long long)gm*p.ldc + gn;
      c[0] += v0 + p.bias[gn];
      c[1] += v1 + p.bias[gn+1];
    } break;
    case 9: {
      float* c = (float*)p.C + (long long)z*p.sC + (long long)gm*p.ldc + gn;
      c[0] = v0; c[1] = v1;
    } break;
    case 12: {
      float a = v0 + p.bias[gn], b2 = v1 + p.bias[gn+1];
      a = a>0.f?a:0.f; b2 = b2>0.f?b2:0.f;
      int b = gm / NIN, r = gm - b*NIN;
      int t1, t2 = -1;
      if (r < 10) t1 = r + 1;
      else if (r < 170){ t1 = r + 1; if (r < 19)  t2 = r + 161;  }
      else            { t1 = r + 10; if (r < 254) t2 = r + 6010; }
      float* Hh = (float*)p.out2;
      float2 val; val.x = a; val.y = b2;
      *(float2*)(Hh + ((long long)b*NT + t1)*Dd + gn) = val;
      if (t2 >= 0)
        *(float2*)(Hh + ((long long)b*NT + t2)*Dd + gn) = val;
    } break;
    case 13: {
      __half* t = (__half*)p.out2 + (long long)z*p.sC;
      t[(long long)gn*LM + gm]     = __float2half_rn(v0);
      t[(long long)(gn+1)*LM + gm] = __float2half_rn(v1);
    } break;
  }
}

// ---------------- cp.async ----------------
__device__ __forceinline__ void cpa16(__half* smem, const __half* g, bool pred){
  uint32_t s = (uint32_t)__cvta_generic_to_shared(smem);
  int sz = pred ? 16 : 0;
  asm volatile("cp.async.cg.shared.global [%0],[%1],16,%2;" :: "r"(s), "l"(g), "r"(sz));
}
__device__ __forceinline__ void cp_commit(){ asm volatile("cp.async.commit_group;"); }
__device__ __forceinline__ void cp_wait0 (){ asm volatile("cp.async.wait_group 0;"); }
__device__ __forceinline__ void cp_wait1 (){ asm volatile("cp.async.wait_group 1;"); }

#define MMA16816(d, a0,a1,a2,a3, b0,b1) \
  asm volatile( \
    "mma.sync.aligned.m16n8k16.row.col.f32.f16.f16.f32 " \
    "{%0,%1,%2,%3},{%4,%5,%6,%7},{%8,%9},{%0,%1,%2,%3};" \
    : "+f"(d[0]), "+f"(d[1]), "+f"(d[2]), "+f"(d[3]) \
    : "r"(a0), "r"(a1), "r"(a2), "r"(a3), "r"(b0), "r"(b1))

// ---------------- fp16 tensor-core batched GEMM (3-stage) ----------------
template<int BM,int BN,int WM,int WN,bool TB>
__global__ void __launch_bounds__(256,2) hgemm_k(GP p){
  constexpr int BK  = 32;
  constexpr int SAK = BK + 8;
  constexpr int SBN = BN + 8;
  constexpr int WC  = BN / WN;
  constexpr int MT  = WM / 16, NTt = WN / 8;
  constexpr int ASZ = BM*SAK;
  constexpr int BSZ = TB ? BN*SAK : BK*SBN;
  static_assert((BM/WM)*(BN/WN) == 8, "8 warps");
  extern __shared__ __half hs[];
  __half* Asb = hs;
  __half* Bsb = hs + 3*ASZ;

  const int tid = threadIdx.x, wid = tid>>5, lane = tid&31;
  const int gid = lane>>2, tig = lane&3;
  const int m0w = (wid / WC) * WM, n0w = (wid % WC) * WN;
  const int z  = blockIdx.z;
  const int zb = z / p.ksplit, ks = z % p.ksplit;
  const int klen = p.K / p.ksplit, kb = ks*klen;
  const __half* A  = p.A + (long long)zb * p.sA;
  const __half* Bm = p.B + (long long)zb * p.sB;
  const int row0 = blockIdx.y * BM, col0 = blockIdx.x * BN;

  auto loadA = [&](int stg, int kt){
    __half* As = Asb + stg*ASZ;
    #pragma unroll
    for(int t=0;t<(BM*BK/8)/256;t++){
      int i = tid + t*256;
      int m = i/(BK/8), kc = (i%(BK/8))*8;
      int gm = row0 + m;
      cpa16(&As[m*SAK + kc], A + (long long)gm*p.lda + kt + kc, gm < p.M);
    }
  };
  auto loadB = [&](int stg, int kt){
    __half* Bs = Bsb + stg*BSZ;
    if (TB){
      #pragma unroll
      for(int t=0;t<(BN*BK/8)/256;t++){
        int i = tid + t*256;
        int n = i/(BK/8), kc = (i%(BK/8))*8;
        cpa16(&Bs[n*SAK + kc], Bm + (long long)(col0+n)*p.ldb + kt + kc, true);
      }
    } else {
      #pragma unroll
      for(int t=0;t<(BK*BN/8)/256;t++){
        int i = tid + t*256;
        int n8 = i % (BN/8), k = i / (BN/8);
        cpa16(&Bs[k*SBN + 8*n8], Bm + (long long)(kt+k)*p.ldb + col0 + 8*n8, true);
      }
    }
  };

  float acc[MT][NTt][4];
  #pragma unroll
  for(int i=0;i<MT;i++)
    #pragma unroll
    for(int j=0;j<NTt;j++)
      #pragma unroll
      for(int q=0;q<4;q++) acc[i][j][q]=0.f;

  const int ntiles = klen / BK;
  loadA(0, kb); loadB(0, kb); cp_commit();
  if (ntiles > 1){ loadA(1, kb + BK); loadB(1, kb + BK); }
  cp_commit();

  for(int it=0; it<ntiles; ++it){
    cp_wait1(); __syncthreads();
    if (it+2 < ntiles){
      int stn = (it+2)%3;
      loadA(stn, kb + (it+2)*BK);
      loadB(stn, kb + (it+2)*BK);
    }
    cp_commit();
    const int stg = it % 3;
    const __half* As = Asb + stg*ASZ;
    const __half* Bs = Bsb + stg*BSZ;
    #pragma unroll
    for(int kk=0;kk<BK/16;kk++){
      const int k0 = kk*16;
      uint32_t af[MT][4], bf[NTt][2];
      #pragma unroll
      for(int mt=0;mt<MT;mt++){
        int m = m0w + mt*16 + gid;
        const __half* a0 = &As[(m  )*SAK + k0 + 2*tig];
        const __half* a1 = &As[(m+8)*SAK + k0 + 2*tig];
        af[mt][0] = *(const uint32_t*)a0;
        af[mt][1] = *(const uint32_t*)a1;
        af[mt][2] = *(const uint32_t*)(a0 + 8);
        af[mt][3] = *(const uint32_t*)(a1 + 8);
      }
      #pragma unroll
      for(int nt=0;nt<NTt;nt++){
        int n = n0w + nt*8 + gid;
        if (TB){
          const __half* b0 = &Bs[n*SAK + k0 + 2*tig];
          bf[nt][0] = *(const uint32_t*)b0;
          bf[nt][1] = *(const uint32_t*)(b0 + 8);
        } else {
          int kr = k0 + 2*tig;
          uint32_t l0 = __half_as_ushort(Bs[(kr  )*SBN + n]);
          uint32_t h0 = __half_as_ushort(Bs[(kr+1)*SBN + n]);
          uint32_t l1 = __half_as_ushort(Bs[(kr+8)*SBN + n]);
          uint32_t h1 = __half_as_ushort(Bs[(kr+9)*SBN + n]);
          bf[nt][0] = l0 | (h0<<16);
          bf[nt][1] = l1 | (h1<<16);
        }
      }
      #pragma unroll
      for(int mt=0;mt<MT;mt++)
        #pragma unroll
        for(int nt=0;nt<NTt;nt++)
          MMA16816(acc[mt][nt], af[mt][0],af[mt][1],af[mt][2],af[mt][3],
                   bf[nt][0],bf[nt][1]);
    }
  }

  #pragma unroll
  for(int mt=0;mt<MT;mt++){
    int r = row0 + m0w + mt*16 + gid;
    #pragma unroll
    for(int nt=0;nt<NTt;nt++){
      int c = col0 + n0w + nt*8 + tig*2;
      if (r < p.M)   epi2_store(p, z, r,   c, acc[mt][nt][0], acc[mt][nt][1]);
      if (r+8 < p.M) epi2_store(p, z, r+8, c, acc[mt][nt][2], acc[mt][nt][3]);
    }
  }
}

constexpr int SMEM_CBIG_TB = 3*(128*40 + 128*40)*2;  // 61440
constexpr int SMEM_C64     = 3*( 64*40 + 32*72 )*2;  // 29184

// ---------------- cooperative pinv chain ----------------
__global__ void __launch_bounds__(256,1) pinv_coop_k(
    const __half* __restrict__ A2,
    __half* Za, __half* Zb, __half* AZa, __half* AZb,
    __half* T1a, __half* T1b, __half* T2, __half* T3){
  cg::grid_group grid = cg::this_grid();
  __shared__ __half As[2][128*40];
  __shared__ __half Bs[2][32*136];

  const int tid = threadIdx.x, wid = tid>>5, lane = tid&31;
  const int gid = lane>>2, tig = lane&3;
  const int m0w = (wid>>1)*32, n0w = (wid&1)*64;
  const int bh = blockIdx.x >> 2;
  const int mi = (blockIdx.x >> 1) & 1, ni = blockIdx.x & 1;
  const long long mb = (long long)bh*65536;
  const int row0 = mi*128, col0 = ni*128;

  auto gemm = [&](const __half* A, const __half* B, int epi, __half* C, __half* C2){
    __syncthreads();
    const __half* Ap = A + mb + (long long)row0*256;
    const __half* Bp = B + mb;

    auto loadA = [&](int stg, int kt){
      #pragma unroll
      for(int t=0;t<2;t++){
        int i = tid + t*256;
        int m = i>>2, kc = (i&3)*8;
        cpa16(&As[stg][m*40 + kc], Ap + (long long)m*256 + kt + kc, true);
      }
    };
    auto loadB = [&](int stg, int kt){
      #pragma unroll
      for(int t=0;t<2;t++){
        int i = tid + t*256;
        int n8 = i & 15, k = i >> 4;
        cpa16(&Bs[stg][k*136 + 8*n8], Bp + (long long)(kt+k)*256 + col0 + 8*n8, true);
      }
    };

    float acc[2][8][4];
    #pragma unroll
    for(int i=0;i<2;i++)
      #pragma unroll
      for(int j=0;j<8;j++)
        #pragma unroll
        for(int q=0;q<4;q++) acc[i][j][q]=0.f;

    loadA(0,0); loadB(0,0); cp_commit();
    for(int it=0; it<8; ++it){
      cp_wait0(); __syncthreads();
      const int stg = it & 1;
      if (it+1 < 8){ loadA(stg^1,(it+1)*32); loadB(stg^1,(it+1)*32); cp_commit(); }
      #pragma unroll
      for(int kk=0;kk<2;kk++){
        const int k0 = kk*16;
        uint32_t af[2][4], bf[8][2];
        #pragma unroll
        for(int mt=0;mt<2;mt++){
          int m = m0w + mt*16 + gid;
          const __half* a0 = &As[stg][(m  )*40 + k0 + 2*tig];
          const __half* a1 = &As[stg][(m+8)*40 + k0 + 2*tig];
          af[mt][0] = *(const uint32_t*)a0;
          af[mt][1] = *(const uint32_t*)a1;
          af[mt][2] = *(const uint32_t*)(a0+8);
          af[mt][3] = *(const uint32_t*)(a1+8);
        }
        int kr = k0 + 2*tig;
        #pragma unroll
        for(int nt=0;nt<8;nt++){
          int n = n0w + nt*8 + gid;
          uint32_t l0 = __half_as_ushort(Bs[stg][(kr  )*136 + n]);
          uint32_t h0 = __half_as_ushort(Bs[stg][(kr+1)*136 + n]);
          uint32_t l1 = __half_as_ushort(Bs[stg][(kr+8)*136 + n]);
          uint32_t h1 = __half_as_ushort(Bs[stg][(kr+9)*136 + n]);
          bf[nt][0] = l0 | (h0<<16);
          bf[nt][1] = l1 | (h1<<16);
        }
        #pragma unroll
        for(int mt=0;mt<2;mt++)
          #pragma unroll
          for(int nt=0;nt<8;nt++)
            MMA16816(acc[mt][nt], af[mt][0],af[mt][1],af[mt][2],af[mt][3],
                     bf[nt][0],bf[nt][1]);
      }
      __syncthreads();
    }

    #pragma unroll
    for(int mt=0;mt<2;mt++){
      #pragma unroll
      for(int nt=0;nt<8;nt++){
        int c = col0 + n0w + nt*8 + tig*2;
        #pragma unroll
        for(int hrow=0;hrow<2;hrow++){
          int r = row0 + m0w + mt*16 + gid + hrow*8;
          float v0 = acc[mt][nt][hrow*2], v1 = acc[mt][nt][hrow*2+1];
          long long o = mb + (long long)r*256 + c;
          float d0 = (r==c)?1.f:0.f, d1 = (r==c+1)?1.f:0.f;
          switch(epi){
            case 0:
              *(__half2*)(C + o)  = __floats2half2_rn(v0, v1);
              *(__half2*)(C2 + o) = __floats2half2_rn(7.f*d0 - v0, 7.f*d1 - v1);
              break;
            case 1:
              *(__half2*)(C + o) = __floats2half2_rn(15.f*d0 - v0, 15.f*d1 - v1);
              break;
            case 2:
              *(__half2*)(C + o) = __floats2half2_rn(13.f*d0 - v0, 13.f*d1 - v1);
              break;
            case 3:
              *(__half2*)(C + o) = __floats2half2_rn(0.25f*v0, 0.25f*v1);
              break;
            case 4: {
              float a = 0.25f*v0, b = 0.25f*v1;
              *(__half2*)(C + o)  = __floats2half2_rn(a, b);
              *(__half2*)(C2 + o) = __floats2half2_rn(7.f*d0 - a, 7.f*d1 - b);
            } break;
          }
        }
      }
    }
  };

  gemm(A2, Za, 0, AZa, T1a);
  grid.sync();

  __half *z=Za, *zn=Zb, *AZ=AZa, *AZn=AZb, *T1=T1a, *T1n=T1b;
  for(int it=0;it<6;it++){
    gemm(AZ, T1, 1, T2, nullptr);
    grid.sync();
    gemm(AZ, T2, 2, T3, nullptr);
    grid.sync();
    gemm(z, T3, 3, zn, nullptr);
    if (it < 5) gemm(AZ, T3, 4, AZn, T1n);
    grid.sync();
    __half* t;
    t=z; z=zn; zn=t;
    t=AZ; AZ=AZn; AZn=t;
    t=T1; T1=T1n; T1n=t;
  }
}

// ---------------- flash-fused a3v (pad-skip) ----------------
__global__ void __launch_bounds__(256,2) fla3v_k(const __half* __restrict__ QL,
                                                 const __half* __restrict__ K,
                                                 const __half* __restrict__ V,
                                                 float* __restrict__ A3VF,
                                                 float* __restrict__ SSUM){
  extern __shared__ __half smf[];
  __half* QLs = smf;
  __half* Ks0 = QLs + 128*72;
  __half* Vs0 = Ks0 + 2*64*72;
  __half* Es  = Vs0 + 2*64*72;

  const int tid = threadIdx.x, wid = tid>>5, lane = tid&31;
  const int gid = lane>>2, tig = lane&3;
  const int wr = wid>>1, wc = wid&1;
  const int m0w = wr*32;
  const int bh = blockIdx.z;
  const int m0 = blockIdx.x*128;
  const int t0base = blockIdx.y*640;
  // tokens 0..127 are exact zero-pads: skipped; SSUM pre-initialized to 128.
  const int itStart = (blockIdx.y == 0) ? 2 : 0;

  const __half* QLp = QL + (long long)bh*LM*DH + (long long)m0*DH;
  const __half* Kp  = K + (long long)bh*NP*DH;
  const __half* Vp  = V + (long long)bh*NP*DH;

  #pragma unroll
  for(int t=0;t<4;t++){
    int i = tid + t*256;
    int m = i>>3, c8 = (i&7)*8;
    cpa16(&QLs[m*72 + c8], QLp + m*DH + c8, true);
  }
  auto loadKV = [&](int stg, int t0){
    __half* Ks = Ks0 + stg*64*72;
    __half* Vs = Vs0 + stg*64*72;
    #pragma unroll
    for(int t=0;t<2;t++){
      int i = tid + t*256;
      int r = i>>3, c8 = (i&7)*8;
      cpa16(&Ks[r*72 + c8], Kp + (long long)(t0+r)*DH + c8, true);
      cpa16(&Vs[r*72 + c8], Vp + (long long)(t0+r)*DH + c8, true);
    }
  };
  loadKV(itStart & 1, t0base + itStart*64); cp_commit();

  float acc2[2][4][4];
  #pragma unroll
  for(int mt=0;mt<2;mt++)
    #pragma unroll
    for(int nt=0;nt<4;nt++)
      #pragma unroll
      for(int q=0;q<4;q++) acc2[mt][nt][q]=0.f;
  float rs[2][2] = {{0.f,0.f},{0.f,0.f}};

  for(int it=itStart; it<10; ++it){
    cp_wait0(); __syncthreads();
    const int stg = it & 1;
    __half* Ks = Ks0 + stg*64*72;
    __half* Vs = Vs0 + stg*64*72;
    if (it < 9){ loadKV(stg^1, t0base + (it+1)*64); cp_commit(); }

    float acc1[2][4][4];
    #pragma unroll
    for(int mt=0;mt<2;mt++)
      #pragma unroll
      for(int nt=0;nt<4;nt++)
        #pragma unroll
        for(int q=0;q<4;q++) acc1[mt][nt][q]=0.f;

    #pragma unroll
    for(int kk=0;kk<4;kk++){
      const int k0 = kk*16;
      uint32_t af[2][4], bf[4][2];
      #pragma unroll
      for(int mt=0;mt<2;mt++){
        int m = m0w + mt*16 + gid;
        const __half* a0 = &QLs[(m  )*72 + k0 + 2*tig];
        const __half* a1 = &QLs[(m+8)*72 + k0 + 2*tig];
        af[mt][0] = *(const uint32_t*)a0;
        af[mt][1] = *(const uint32_t*)a1;
        af[mt][2] = *(const uint32_t*)(a0+8);
        af[mt][3] = *(const uint32_t*)(a1+8);
      }
      #pragma unroll
      for(int nt=0;nt<4;nt++){
        int n = wc*32 + nt*8 + gid;
        const __half* b0 = &Ks[n*72 + k0 + 2*tig];
        bf[nt][0] = *(const uint32_t*)b0;
        bf[nt][1] = *(const uint32_t*)(b0+8);
      }
      #pragma unroll
      for(int mt=0;mt<2;mt++)
        #pragma unroll
        for(int nt=0;nt<4;nt++)
          MMA16816(acc1[mt][nt], af[mt][0],af[mt][1],af[mt][2],af[mt][3],
                   bf[nt][0],bf[nt][1]);
    }

    #pragma unroll
    for(int mt=0;mt<2;mt++){
      int r = m0w + mt*16 + gid;
      #pragma unroll
      for(int nt=0;nt<4;nt++){
        int c = wc*32 + nt*8 + tig*2;
        float e0 = __expf(acc1[mt][nt][0]), e1 = __expf(acc1[mt][nt][1]);
        float e2 = __expf(acc1[mt][nt][2]), e3 = __expf(acc1[mt][nt][3]);
        rs[mt][0] += e0 + e1;
        rs[mt][1] += e2 + e3;
        *(__half2*)(Es + (r  )*72 + c) = __floats2half2_rn(e0, e1);
        *(__half2*)(Es + (r+8)*72 + c) = __floats2half2_rn(e2, e3);
      }
    }
    __syncthreads();

    #pragma unroll
    for(int kk=0;kk<4;kk++){
      const int k0 = kk*16;
      uint32_t af[2][4], bf[4][2];
      #pragma unroll
      for(int mt=0;mt<2;mt++){
        int m = m0w + mt*16 + gid;
        const __half* a0 = &Es[(m  )*72 + k0 + 2*tig];
        const __half* a1 = &Es[(m+8)*72 + k0 + 2*tig];
        af[mt][0] = *(const uint32_t*)a0;
        af[mt][1] = *(const uint32_t*)a1;
        af[mt][2] = *(const uint32_t*)(a0+8);
        af[mt][3] = *(const uint32_t*)(a1+8);
      }
      int kr = k0 + 2*tig;
      #pragma unroll
      for(int nt=0;nt<4;nt++){
        int n = wc*32 + nt*8 + gid;
        uint32_t l0 = __half_as_ushort(Vs[(kr  )*72 + n]);
        uint32_t h0 = __half_as_ushort(Vs[(kr+1)*72 + n]);
        uint32_t l1 = __half_as_ushort(Vs[(kr+8)*72 + n]);
        uint32_t h1 = __half_as_ushort(Vs[(kr+9)*72 + n]);
        bf[nt][0] = l0 | (h0<<16);
        bf[nt][1] = l1 | (h1<<16);
      }
      #pragma unroll
      for(int mt=0;mt<2;mt++)
        #pragma unroll
        for(int nt=0;nt<4;nt++)
          MMA16816(acc2[mt][nt], af[mt][0],af[mt][1],af[mt][2],af[mt][3],
                   bf[nt][0],bf[nt][1]);
    }
  }

  float* outA = A3VF + (long long)bh*LM*DH + (long long)m0*DH;
  #pragma unroll
  for(int mt=0;mt<2;mt++){
    int r = m0w + mt*16 + gid;
    #pragma unroll
    for(int nt=0;nt<4;nt++){
      int c = wc*32 + nt*8 + tig*2;
      atomicAdd(outA + (long long)r*DH + c,       acc2[mt][nt][0]);
      atomicAdd(outA + (long long)r*DH + c + 1,   acc2[mt][nt][1]);
      atomicAdd(outA + (long long)(r+8)*DH + c,   acc2[mt][nt][2]);
      atomicAdd(outA + (long long)(r+8)*DH + c+1, acc2[mt][nt][3]);
    }
  }
  #pragma unroll
  for(int mt=0;mt<2;mt++){
    float s0 = rs[mt][0], s1 = rs[mt][1];
    s0 += __shfl_xor_sync(0xffffffffu, s0, 1);
    s0 += __shfl_xor_sync(0xffffffffu, s0, 2);
    s1 += __shfl_xor_sync(0xffffffffu, s1, 1);
    s1 += __shfl_xor_sync(0xffffffffu, s1, 2);
    if (tig == 0){
      int r = m0w + mt*16 + gid;
      atomicAdd(SSUM + bh*LM + m0 + r,     s0);
      atomicAdd(SSUM + bh*LM + m0 + r + 8, s1);
    }
  }
}

__global__ void zero_acc_k(float* __restrict__ a, float* __restrict__ b){
  int i = blockIdx.x*256 + threadIdx.x;
  a[i] = 0.f;
  if (i < 8192) b[i] = 128.f;   // 128 skipped zero-pad tokens contribute exp(0)=1 each
}

__global__ void norm_a3v_k(const float* __restrict__ A3VF, const float* __restrict__ SS,
                           __half* __restrict__ O){
  int i = blockIdx.x*256 + threadIdx.x;
  int bh = i>>14, l = (i>>6)&255;
  O[i] = __float2half_rn(A3VF[i] / SS[bh*256 + l]);
}

// ---------------- fused GEMM(K=64,N=256) + row softmax ----------------
__global__ void __launch_bounds__(256) fsm_k(GP p){
  __shared__ __half As[64*72];
  __shared__ __half Bs[256*72];
  __shared__ float redm[64][2];
  __shared__ float reds[64][2];

  const int tid = threadIdx.x, wid = tid>>5, lane = tid&31;
  const int gid = lane>>2, tig = lane&3;
  const int m0w = (wid>>1)*16, wc = wid&1, n0w = wc*128;
  const int z = blockIdx.y;
  const int row0 = blockIdx.x*64;
  const __half* A  = p.A + (long long)z*p.sA;
  const __half* Bm = p.B + (long long)z*p.sB;
  __half* C = (__half*)p.C + (long long)z*p.sC;

  #pragma unroll
  for(int t=0;t<2;t++){
    int i = tid + t*256;
    int m = i>>3, c8 = (i&7)*8;
    int gm = row0 + m;
    uint4 v = make_uint4(0,0,0,0);
    if (gm < p.M) v = *(const uint4*)(A + (long long)gm*p.lda + c8);
    *(uint4*)&As[m*72 + c8] = v;
  }
  #pragma unroll
  for(int t=0;t<8;t++){
    int i = tid + t*256;
    int n = i>>3, c8 = (i&7)*8;
    *(uint4*)&Bs[n*72 + c8] = *(const uint4*)(Bm + (long long)n*p.ldb + c8);
  }
  __syncthreads();

  float acc[16][4];
  #pragma unroll
  for(int j=0;j<16;j++){ acc[j][0]=0;acc[j][1]=0;acc[j][2]=0;acc[j][3]=0; }

  #pragma unroll
  for(int kk=0;kk<4;kk++){
    const int k0 = kk*16;
    int m = m0w + gid;
    const __half* a0 = &As[(m  )*72 + k0 + 2*tig];
    const __half* a1 = &As[(m+8)*72 + k0 + 2*tig];
    uint32_t af0 = *(const uint32_t*)a0;
    uint32_t af1 = *(const uint32_t*)a1;
    uint32_t af2 = *(const uint32_t*)(a0+8);
    uint32_t af3 = *(const uint32_t*)(a1+8);
    #pragma unroll
    for(int nt=0;nt<16;nt++){
      int n = n0w + nt*8 + gid;
      const __half* b0 = &Bs[n*72 + k0 + 2*tig];
      uint32_t bf0 = *(const uint32_t*)b0;
      uint32_t bf1 = *(const uint32_t*)(b0+8);
      MMA16816(acc[nt], af0,af1,af2,af3, bf0,bf1);
    }
  }

  int rl1 = m0w + gid, rl2 = rl1 + 8;
  float m1 = -3.4e38f, m2 = -3.4e38f;
  #pragma unroll
  for(int nt=0;nt<16;nt++){
    m1 = fmaxf(m1, fmaxf(acc[nt][0], acc[nt][1]));
    m2 = fmaxf(m2, fmaxf(acc[nt][2], acc[nt][3]));
  }
  m1 = fmaxf(m1, __shfl_xor_sync(0xffffffffu, m1, 1));
  m1 = fmaxf(m1, __shfl_xor_sync(0xffffffffu, m1, 2));
  m2 = fmaxf(m2, __shfl_xor_sync(0xffffffffu, m2, 1));
  m2 = fmaxf(m2, __shfl_xor_sync(0xffffffffu, m2, 2));
  if (tig == 0){ redm[rl1][wc] = m1; redm[rl2][wc] = m2; }
  __syncthreads();
  float M1 = fmaxf(redm[rl1][0], redm[rl1][1]);
  float M2 = fmaxf(redm[rl2][0], redm[rl2][1]);
  float s1 = 0.f, s2 = 0.f;
  #pragma unroll
  for(int nt=0;nt<16;nt++){
    acc[nt][0] = __expf(acc[nt][0]-M1); s1 += acc[nt][0];
    acc[nt][1] = __expf(acc[nt][1]-M1); s1 += acc[nt][1];
    acc[nt][2] = __expf(acc[nt][2]-M2); s2 += acc[nt][2];
    acc[nt][3] = __expf(acc[nt][3]-M2); s2 += acc[nt][3];
  }
  s1 += __shfl_xor_sync(0xffffffffu, s1, 1);
  s1 += __shfl_xor_sync(0xffffffffu, s1, 2);
  s2 += __shfl_xor_sync(0xffffffffu, s2, 1);
  s2 += __shfl_xor_sync(0xffffffffu, s2, 2);
  if (tig == 0){ reds[rl1][wc] = s1; reds[rl2][wc] = s2; }
  __syncthreads();
  float i1 = 1.f/(reds[rl1][0] + reds[rl1][1]);
  float i2 = 1.f/(reds[rl2][0] + reds[rl2][1]);

  int r1 = row0 + rl1, r2 = row0 + rl2;
  #pragma unroll
  for(int nt=0;nt<16;nt++){
    int c = n0w + nt*8 + tig*2;
    if (r1 < p.M)
      *(__half2*)(C + (long long)r1*p.ldc + c) = __floats2half2_rn(acc[nt][0]*i1, acc[nt][1]*i1);
    if (r2 < p.M)
      *(__half2*)(C + (long long)r2*p.ldc + c) = __floats2half2_rn(acc[nt][2]*i2, acc[nt][3]*i2);
  }
}

// ---------------- fused attention: softmax(Q@KL^T) @ W2T -> ATT += ----------------
// p.C = W2T per-bh [64][256] (stride p.sC = 16384)
__global__ void __launch_bounds__(256) fattn_k(GP p){
  extern __shared__ __half smx[];
  __half* As = smx;              // 64*72
  __half* Bs = smx + 64*72;      // 256*72 ; reused as scores [64][264]
  __half* Ws = Bs + 256*72;      // 64*264 (W2T: [d][l], stride 264)
  __shared__ float redm[64][2];
  __shared__ float reds[64][2];

  const int tid = threadIdx.x, wid = tid>>5, lane = tid&31;
  const int gid = lane>>2, tig = lane&3;
  const int m0w = (wid>>1)*16, wc = wid&1, n0w = wc*128;
  const int z = blockIdx.y;
  const int row0 = blockIdx.x*64;
  const __half* A  = p.A + (long long)z*p.sA;
  const __half* Bm = p.B + (long long)z*p.sB;
  const __half* W2p = (const __half*)p.C + (long long)z*p.sC;
  __half* att = (__half*)p.out2;
  const int b = z>>3, hh = z&7;

  #pragma unroll
  for(int t=0;t<2;t++){
    int i = tid + t*256;
    int m = i>>3, c8 = (i&7)*8;
    int gm = row0 + m;
    uint4 v = make_uint4(0,0,0,0);
    if (gm < p.M) v = *(const uint4*)(A + (long long)gm*p.lda + c8);
    *(uint4*)&As[m*72 + c8] = v;
  }
  #pragma unroll
  for(int t=0;t<8;t++){
    int i = tid + t*256;
    int n = i>>3, c8 = (i&7)*8;
    *(uint4*)&Bs[n*72 + c8] = *(const uint4*)(Bm + (long long)n*p.ldb + c8);
  }
  // W2T [64][256] -> Ws stride 264
  #pragma unroll
  for(int t=0;t<8;t++){
    int i = tid + t*256;
    int d = i>>5, c8 = (i&31)*8;
    *(uint4*)&Ws[d*264 + c8] = *(const uint4*)(W2p + d*256 + c8);
  }
  __syncthreads();

  float acc[16][4];
  #pragma unroll
  for(int j=0;j<16;j++){ acc[j][0]=0;acc[j][1]=0;acc[j][2]=0;acc[j][3]=0; }

  #pragma unroll
  for(int kk=0;kk<4;kk++){
    const int k0 = kk*16;
    int m = m0w + gid;
    const __half* a0 = &As[(m  )*72 + k0 + 2*tig];
    const __half* a1 = &As[(m+8)*72 + k0 + 2*tig];
    uint32_t af0 = *(const uint32_t*)a0;
    uint32_t af1 = *(const uint32_t*)a1;
    uint32_t af2 = *(const uint32_t*)(a0+8);
    uint32_t af3 = *(const uint32_t*)(a1+8);
    #pragma unroll
    for(int nt=0;nt<16;nt++){
      int n = n0w + nt*8 + gid;
      const __half* b0 = &Bs[n*72 + k0 + 2*tig];
      uint32_t bf0 = *(const uint32_t*)b0;
      uint32_t bf1 = *(const uint32_t*)(b0+8);
      MMA16816(acc[nt], af0,af1,af2,af3, bf0,bf1);
    }
  }

  int rl1 = m0w + gid, rl2 = rl1 + 8;
  float m1 = -3.4e38f, m2 = -3.4e38f;
  #pragma unroll
  for(int nt=0;nt<16;nt++){
    m1 = fmaxf(m1, fmaxf(acc[nt][0], acc[nt][1]));
    m2 = fmaxf(m2, fmaxf(acc[nt][2], acc[nt][3]));
  }
  m1 = fmaxf(m1, __shfl_xor_sync(0xffffffffu, m1, 1));
  m1 = fmaxf(m1, __shfl_xor_sync(0xffffffffu, m1, 2));
  m2 = fmaxf(m2, __shfl_xor_sync(0xffffffffu, m2, 1));
  m2 = fmaxf(m2, __shfl_xor_sync(0xffffffffu, m2, 2));
  if (tig == 0){ redm[rl1][wc] = m1; redm[rl2][wc] = m2; }
  __syncthreads();
  float M1 = fmaxf(redm[rl1][0], redm[rl1][1]);
  float M2 = fmaxf(redm[rl2][0], redm[rl2][1]);
  float s1 = 0.f, s2 = 0.f;
  #pragma unroll
  for(int nt=0;nt<16;nt++){
    acc[nt][0] = __expf(acc[nt][0]-M1); s1 += acc[nt][0];
    acc[nt][1] = __expf(acc[nt][1]-M1); s1 += acc[nt][1];
    acc[nt][2] = __expf(acc[nt][2]-M2); s2 += acc[nt][2];
    acc[nt][3] = __expf(acc[nt][3]-M2); s2 += acc[nt][3];
  }
  s1 += __shfl_xor_sync(0xffffffffu, s1, 1);
  s1 += __shfl_xor_sync(0xffffffffu, s1, 2);
  s2 += __shfl_xor_sync(0xffffffffu, s2, 1);
  s2 += __shfl_xor_sync(0xffffffffu, s2, 2);
  if (tig == 0){ reds[rl1][wc] = s1; reds[rl2][wc] = s2; }
  __syncthreads();
  float i1 = 1.f/(reds[rl1][0] + reds[rl1][1]);
  float i2 = 1.f/(reds[rl2][0] + reds[rl2][1]);

  __half* Sc = Bs;
  #pragma unroll
  for(int nt=0;nt<16;nt++){
    int c = n0w + nt*8 + tig*2;
    *(__half2*)(Sc + rl1*264 + c) = __floats2half2_rn(acc[nt][0]*i1, acc[nt][1]*i1);
    *(__half2*)(Sc + rl2*264 + c) = __floats2half2_rn(acc[nt][2]*i2, acc[nt][3]*i2);
  }
  __syncthreads();

  float a2c[4][4];
  #pragma unroll
  for(int j=0;j<4;j++){ a2c[j][0]=0;a2c[j][1]=0;a2c[j][2]=0;a2c[j][3]=0; }

  #pragma unroll
  for(int kk=0;kk<16;kk++){
    const int k0 = kk*16;
    int m = m0w + gid;
    const __half* a0 = &Sc[(m  )*264 + k0 + 2*tig];
    const __half* a1 = &Sc[(m+8)*264 + k0 + 2*tig];
    uint32_t af0 = *(const uint32_t*)a0;
    uint32_t af1 = *(const uint32_t*)a1;
    uint32_t af2 = *(const uint32_t*)(a0+8);
    uint32_t af3 = *(const uint32_t*)(a1+8);
    #pragma unroll
    for(int nt=0;nt<4;nt++){
      int n = wc*32 + nt*8 + gid;
      const __half* b0 = &Ws[n*264 + k0 + 2*tig];
      uint32_t bf0 = *(const uint32_t*)b0;
      uint32_t bf1 = *(const uint32_t*)(b0+8);
      MMA16816(a2c[nt], af0,af1,af2,af3, bf0,bf1);
    }
  }

  int r1 = row0 + rl1, r2 = row0 + rl2;
  #pragma unroll
  for(int nt=0;nt<4;nt++){
    int c = wc*32 + nt*8 + tig*2;
    if (r1 < p.M){
      __half2* o = (__half2*)(att + ((long long)b*NP + PADT + r1)*Dd + hh*DH + c);
      __half2 old = *o;
      *o = __floats2half2_rn(__low2float(old)+a2c[nt][0], __high2float(old)+a2c[nt][1]);
    }
    if (r2 < p.M){
      __half2* o = (__half2*)(att + ((long long)b*NP + PADT + r2)*Dd + hh*DH + c);
      __half2 old = *o;
      *o = __floats2half2_rn(__low2float(old)+a2c[nt][2], __high2float(old)+a2c[nt][3]);
    }
  }
}

// ---------------- pre-round / transpose ----------------
__global__ void rc_half4_k(const float* __restrict__ s, __half* __restrict__ d, int n4){
  int i = blockIdx.x*256 + threadIdx.x;
  if (i < n4){
    float4 v = ((const float4*)s)[i];
    ((__half2*)d)[2*i]   = __floats2half2_rn(v.x, v.y);
    ((__half2*)d)[2*i+1] = __floats2half2_rn(v.z, v.w);
  }
}
__global__ void rc_trans_k(const float* __restrict__ s, __half* __restrict__ d,
                           int K, int N){
  int i = blockIdx.x*256 + threadIdx.x;
  if (i < K*N){ int k = i / N, n = i % N; d[(long long)n*K + k] = __float2half_rn(s[i]); }
}

// ---------------- small kernels ----------------
__global__ void cls_k(const float* __restrict__ cls, float* __restrict__ Hb){
  int b = blockIdx.x;
  Hb[(long long)b*NT*Dd + threadIdx.x]       = cls[threadIdx.x];
  Hb[(long long)b*NT*Dd + threadIdx.x + 256] = cls[threadIdx.x + 256];
}

__global__ void ln_pad_k(const float* __restrict__ Hin, const float* __restrict__ g,
                         const float* __restrict__ bb, __half* __restrict__ XP){
  __shared__ float red[256];
  int n = blockIdx.x, b = blockIdx.y, t = threadIdx.x;
  __half* out = XP + ((long long)b*NP + n)*Dd;
  if (n < PADT){ out[t]=__ushort_as_half((unsigned short)0); out[t+256]=__ushort_as_half((unsigned short)0); return; }
  const float* x = Hin + ((long long)b*NT + (n-PADT))*Dd;
  float v0=x[t], v1=x[t+256];
  red[t]=v0+v1; __syncthreads();
  for(int o=128;o>0;o>>=1){ if(t<o) red[t]+=red[t+o]; __syncthreads(); }
  float mu = red[0]*(1.f/512.f); __syncthreads();
  float d0=v0-mu, d1=v1-mu;
  red[t]=d0*d0+d1*d1; __syncthreads();
  for(int o=128;o>0;o>>=1){ if(t<o) red[t]+=red[t+o]; __syncthreads(); }
  float rs = rsqrtf(red[0]*(1.f/512.f)+1e-5f);
  out[t]     = __float2half_rn(d0*rs*g[t]     + bb[t]);
  out[t+256] = __float2half_rn(d1*rs*g[t+256] + bb[t+256]);
}

__global__ void landmarks_k(const __half* __restrict__ Q, const __half* __restrict__ K,
                            __half* __restrict__ QL, __half* __restrict__ KL){
  int idx = blockIdx.x*256 + threadIdx.x;
  int d = idx & 63; int i = (idx>>6) & 255; int bh = idx >> 14;
  long long base = ((long long)bh*NP + (long long)i*LFAC)*DH + d;
  float sq=0.f, sk=0.f;
  #pragma unroll
  for(int j=0;j<LFAC;j++){
    sq += __half2float(Q[base + (long long)j*DH]);
    sk += __half2float(K[base + (long long)j*DH]);
  }
  QL[idx] = __float2half_rn(sq*(1.f/LFAC));
  KL[idx] = __float2half_rn(sk*(1.f/LFAC));
}

__global__ void pinv_part_k(const __half* __restrict__ A, float* __restrict__ red){
  __shared__ float s1[256], s2[256];
  int bh = blockIdx.x, t = threadIdx.x;
  const __half* a = A + (long long)bh*65536;
  float rs=0.f, cs=0.f;
  for(int c=0;c<256;c++) rs += fabsf(__half2float(a[t*256+c]));
  for(int r=0;r<256;r++) cs += fabsf(__half2float(a[r*256+t]));
  s1[t]=rs; s2[t]=cs; __syncthreads();
  for(int o=128;o>0;o>>=1){ if(t<o){ s1[t]=fmaxf(s1[t],s1[t+o]); s2[t]=fmaxf(s2[t],s2[t+o]); } __syncthreads(); }
  if(t==0){ red[bh]=s1[0]; red[32+bh]=s2[0]; }
}

__global__ void pinv_trans_k(const __half* __restrict__ A, const float* __restrict__ red,
                             __half* __restrict__ Z){
  int bh = blockIdx.x, t = threadIdx.x;
  float col=0.f, row=0.f;
  for(int i=0;i<32;i++){ col=fmaxf(col,red[i]); row=fmaxf(row,red[32+i]); }
  float inv = 1.f/(col*row);
  const __half* a = A + (long long)bh*65536;
  __half* z = Z + (long long)bh*65536;
  for(int i=0;i<256;i++)
    z[i*256+t] = __float2half_rn(__half2float(a[t*256+i])*inv);
}

__global__ void dwconv2_k(const __half* __restrict__ V, const float* __restrict__ w,
                          __half* __restrict__ att){
  __shared__ __half sV[64*72];
  __shared__ float swh[33];
  int bh = blockIdx.y; int b = bh>>3, h = bh&7;
  int tid = threadIdx.x;
  int n0 = PADT + blockIdx.x*32;
  const __half* vb = V + (long long)bh*NP*DH;
  if (tid < 33) swh[tid] = w[h*33 + tid];
  #pragma unroll
  for(int t=0;t<2;t++){
    int i = tid + t*256;
    int n = i>>3, c8 = (i&7)*8;
    int src = n0 - 16 + n;
    uint4 v = make_uint4(0,0,0,0);
    if (src >= 0 && src < NP) v = *(const uint4*)(vb + (long long)src*DH + c8);
    *(uint4*)&sV[n*72 + c8] = v;
  }
  __syncthreads();
  int d = tid & 63, grp = tid >> 6;
  #pragma unroll
  for(int jj=0;jj<8;jj++){
    int jo = grp + jj*4;
    int tok = n0 + jo;
    if (tok >= NP) continue;
    float acc = 0.f;
    #pragma unroll
    for(int t=0;t<33;t++)
      acc += __half2float(sV[(jo+t)*72 + d]) * swh[t];
    att[((long long)b*NP + tok)*Dd + h*DH + d] = __float2half_rn(acc);
  }
}

__global__ void copyrows_k(const float* __restrict__ Hin, float* __restrict__ Hout){
  int t = blockIdx.x, b = blockIdx.y;
  long long o = ((long long)b*NT + t)*Dd;
  Hout[o+threadIdx.x]     = Hin[o+threadIdx.x];
  Hout[o+threadIdx.x+256] = Hin[o+threadIdx.x+256];
}

__global__ void ppeg_tiled_k(const float* __restrict__ Hin, float* __restrict__ Hout,
                             int tok0, int S, int ntx,
                             const float* __restrict__ w7, const float* __restrict__ b7,
                             const float* __restrict__ w5, const float* __restrict__ b5,
                             const float* __restrict__ w3, const float* __restrict__ b3){
  extern __shared__ float sm[];
  float* patch = sm;
  float* swt   = sm + 484*33;
  float* sbias = swt + 32*83;

  const int tid = threadIdx.x;
  const int b  = blockIdx.z;
  const int c0 = blockIdx.y * 32;
  const int ty0 = (blockIdx.x / ntx) * 16;
  const int tx0 = (blockIdx.x % ntx) * 16;
  const float* base = Hin + ((long long)b*NT + tok0)*Dd;

  for(int i=tid;i<32*49;i+=256){ int ch=i/49, t=i%49; swt[ch*83+t]    = w7[(c0+ch)*49+t]; }
  for(int i=tid;i<32*25;i+=256){ int ch=i/25, t=i%25; swt[ch*83+49+t] = w5[(c0+ch)*25+t]; }
  for(int i=tid;i<32*9 ;i+=256){ int ch=i/9 , t=i%9 ; swt[ch*83+74+t] = w3[(c0+ch)*9+t]; }
  if (tid < 32) sbias[tid] = b7[c0+tid] + b5[c0+tid] + b3[c0+tid];

  for(int i=tid;i<484*32;i+=256){
    int px = i>>5, ch = i&31;
    int py = px/22, pxx = px%22;
    int gy = ty0 - 3 + py, gx = tx0 - 3 + pxx;
    float v = 0.f;
    if (gy >= 0 && gy < S && gx >= 0 && gx < S)
      v = base[(long long)(gy*S+gx)*Dd + c0 + ch];
    patch[px*33 + ch] = v;
  }
  __syncthreads();

  const int ch = tid & 31, pg = tid >> 5;
  const float* wch = &swt[ch*83];
  #pragma unroll 1
  for(int jb=0;jb<4;jb++){
    float a[8];
    int pb[8];
    #pragma unroll
    for(int jj=0;jj<8;jj++){
      int px = pg*32 + jb*8 + jj;
      int ty = px >> 4, tx = px & 15;
      pb[jj] = (ty*22 + tx)*33 + ch;
      a[jj] = patch[pb[jj] + (3*22+3)*33] + sbias[ch];
    }
    #pragma unroll 1
    for(int ky=0;ky<7;ky++){
      #pragma unroll
      for(int kx=0;kx<7;kx++){
        float w = wch[ky*7+kx];
        int off = (ky*22+kx)*33;
        #pragma unroll
        for(int jj=0;jj<8;jj++) a[jj] += patch[pb[jj]+off]*w;
      }
    }
    #pragma unroll 1
    for(int ky=0;ky<5;ky++){
      #pragma unroll
      for(int kx=0;kx<5;kx++){
        float w = wch[49+ky*5+kx];
        int off = ((ky+1)*22 + kx+1)*33;
        #pragma unroll
        for(int jj=0;jj<8;jj++) a[jj] += patch[pb[jj]+off]*w;
      }
    }
    #pragma unroll 1
    for(int ky=0;ky<3;ky++){
      #pragma unroll
      for(int kx=0;kx<3;kx++){
        float w = wch[74+ky*3+kx];
        int off = ((ky+2)*22 + kx+2)*33;
        #pragma unroll
        for(int jj=0;jj<8;jj++) a[jj] += patch[pb[jj]+off]*w;
      }
    }
    #pragma unroll
    for(int jj=0;jj<8;jj++){
      int px = pg*32 + jb*8 + jj;
      int oy = ty0 + (px>>4), ox = tx0 + (px&15);
      if (oy < S && ox < S)
        Hout[((long long)b*NT + tok0 + oy*S + ox)*Dd + c0 + ch] = a[jj];
    }
  }
}

__global__ void final_ln_k(const float* __restrict__ Hb, const float* __restrict__ g,
                           const float* __restrict__ bb, float* __restrict__ out){
  __shared__ float red[256];
  int b = blockIdx.x, t = threadIdx.x;
  const float* x = Hb + (long long)b*NT*Dd;
  float v0=x[t], v1=x[t+256];
  red[t]=v0+v1; __syncthreads();
  for(int o=128;o>0;o>>=1){ if(t<o) red[t]+=red[t+o]; __syncthreads(); }
  float mu = red[0]*(1.f/512.f); __syncthreads();
  float d0=v0-mu, d1=v1-mu;
  red[t]=d0*d0+d1*d1; __syncthreads();
  for(int o=128;o>0;o>>=1){ if(t<o) red[t]+=red[t+o]; __syncthreads(); }
  float rs = rsqrtf(red[0]*(1.f/512.f)+1e-5f);
  out[b*Dd + t]     = d0*rs*g[t]     + bb[t];
  out[b*Dd + t+256] = d1*rs*g[t+256] + bb[t+256];
}

// ---------------- host side ----------------
static void tg_big(GP p, int batches, cudaStream_t st){
  dim3 g(p.N / 128, (p.M + 127)/128, batches * p.ksplit);
  hgemm_k<128,128,32,64,true><<<g,256,SMEM_CBIG_TB,st>>>(p);
}
static void tg_64(GP p, int batches, cudaStream_t st){
  dim3 g(p.N / 64, (p.M + 63)/64, batches * p.ksplit);
  hgemm_k<64,64,16,32,false><<<g,256,SMEM_C64,st>>>(p);
}

struct Scratch {
  float  *H,*H2,*RED,*SSUM,*A3VF;
  __half *XR,*WT,*XP,*QKV,*QL,*KL,*A2,*AZa,*T1a,*AZb,*T1b,*T2,*T3,*Za,*Zb,*A3V,*W2,*ATT;
};

struct Streams {
  cudaStream_t stP;
  cudaEvent_t evF, evJ, evC, evD, evW0, evW1;
};

static void attn_layer(float* Hbuf, const float* ng, const float* nb,
                       const __half* qkvwT, const __half* owT, const float* ob,
                       const float* rw, const Scratch& s, const Streams& st){
  __half* Q  = s.QKV;
  __half* Kp = s.QKV + QSZ;
  __half* V  = s.QKV + 2*QSZ;
  GP p{};

  ln_pad_k<<<dim3(NP,Bb),256>>>(Hbuf, ng, nb, s.XP);

  p = {s.XP,(long long)NP*Dd,Dd, qkvwT,0,Dd, nullptr,0,0, NP,3*Dd,Dd, 1,2, nullptr,0.125f, s.QKV};
  tg_big(p,Bb,0);

  zero_acc_k<<<2048,256>>>(s.A3VF, s.SSUM);
  landmarks_k<<<2048,256>>>(Q, Kp, s.QL, s.KL);

  // sim2 = softmax(QL @ KL^T) fused (exact)
  p = {s.QL,(long long)LM*DH,DH, s.KL,(long long)LM*DH,DH, s.A2,(long long)LM*LM,LM, LM,LM,DH,1,0,nullptr,0.f,nullptr};
  fsm_k<<<dim3(4,32),256>>>(p);

  // ---- fork: pinv on stP (single cooperative kernel) ----
  cudaEventRecord(st.evF, 0);
  cudaStreamWaitEvent(st.stP, st.evF, 0);

  pinv_part_k<<<32,256,0,st.stP>>>(s.A2, s.RED);
  pinv_trans_k<<<32,256,0,st.stP>>>(s.A2, s.RED, s.Za);
  {
    void* args[] = {(void*)&s.A2, (void*)&s.Za, (void*)&s.Zb,
                    (void*)&s.AZa, (void*)&s.AZb, (void*)&s.T1a, (void*)&s.T1b,
                    (void*)&s.T2, (void*)&s.T3};
    cudaLaunchCooperativeKernel((void*)pinv_coop_k, dim3(128), dim3(256),
                                args, 0, st.stP);
  }
  cudaEventRecord(st.evJ, st.stP);

  // ---- main stream: flash-fused a3 @ v ----
  fla3v_k<<<dim3(2,10,32),256,73728>>>(s.QL, Kp, V, s.A3VF, s.SSUM);
  norm_a3v_k<<<2048,256>>>(s.A3VF, s.SSUM, s.A3V);

  dwconv2_k<<<dim3((NT+31)/32,32),256>>>(V, rw, s.ATT);

  // ---- join ----
  cudaStreamWaitEvent(0, st.evJ, 0);

  // W2T = (Z @ a3v)^T per bh (final z in Za)
  p = {s.Za,65536,LM, s.A3V,(long long)LM*DH,DH, nullptr,16384,0, LM,DH,LM,1,13,nullptr,0.f,s.W2};
  tg_64(p,32,0);

  // fused: ATT += softmax(q @ KL^T) @ W2
  p = {Q+(long long)PADT*DH,(long long)NP*DH,DH, s.KL,(long long)LM*DH,DH,
       s.W2,16384,0, NT,DH,LM,1,0,nullptr,0.f,s.ATT};
  fattn_k<<<dim3((NT+63)/64,32),256,82944>>>(p);

  // out proj + residual add
  p = {s.ATT+(long long)PADT*Dd,(long long)NP*Dd,Dd, owT,0,Dd, Hbuf,(long long)NT*Dd,Dd,
       NT,Dd,Dd,1,6,ob,0.f,nullptr};
  tg_big(p,Bb,0);
}

extern "C" void kernel_launch(void* const* d_in, const int* in_sizes, int n_in,
                              void* d_out, int out_size){
  const float* x        = (const float*)d_in[0];
  const float* fc1_w    = (const float*)d_in[1];
  const float* fc1_b    = (const float*)d_in[2];
  const float* cls_tok  = (const float*)d_in[3];
  const float* l1_ng    = (const float*)d_in[4];
  const float* l1_nb    = (const float*)d_in[5];
  const float* l1_qkv   = (const float*)d_in[6];
  const float* l1_ow    = (const float*)d_in[7];
  const float* l1_ob    = (const float*)d_in[8];
  const float* l1_rw    = (const float*)d_in[9];
  const float* ct_w7    = (const float*)d_in[10];
  const float* ct_b7    = (const float*)d_in[11];
  const float* ct_w5    = (const float*)d_in[12];
  const float* ct_b5    = (const float*)d_in[13];
  const float* ct_w3    = (const float*)d_in[14];
  const float* ct_b3    = (const float*)d_in[15];
  const float* pth_w7   = (const float*)d_in[16];
  const float* pth_b7   = (const float*)d_in[17];
  const float* pth_w5   = (const float*)d_in[18];
  const float* pth_b5   = (const float*)d_in[19];
  const float* pth_w3   = (const float*)d_in[20];
  const float* pth_b3   = (const float*)d_in[21];
  const float* l2_ng    = (const float*)d_in[22];
  const float* l2_nb    = (const float*)d_in[23];
  const float* l2_qkv   = (const float*)d_in[24];
  const float* l2_ow    = (const float*)d_in[25];
  const float* l2_ob    = (const float*)d_in[26];
  const float* l2_rw    = (const float*)d_in[27];
  const float* norm_g   = (const float*)d_in[28];
  const float* norm_b   = (const float*)d_in[29];

  Scratch s;
  cudaGetSymbolAddress((void**)&s.H  , g_H  );
  cudaGetSymbolAddress((void**)&s.H2 , g_H2 );
  cudaGetSymbolAddress((void**)&s.RED, g_RED);
  cudaGetSymbolAddress((void**)&s.SSUM,g_SSUM);
  cudaGetSymbolAddress((void**)&s.A3VF,g_A3VF);
  cudaGetSymbolAddress((void**)&s.XR , g_XR );
  cudaGetSymbolAddress((void**)&s.WT , g_WT );
  cudaGetSymbolAddress((void**)&s.XP , g_XP );
  cudaGetSymbolAddress((void**)&s.QKV, g_QKV);
  cudaGetSymbolAddress((void**)&s.QL , g_QL );
  cudaGetSymbolAddress((void**)&s.KL , g_KL );
  cudaGetSymbolAddress((void**)&s.A2 , g_A2 );
  cudaGetSymbolAddress((void**)&s.AZa, g_AZa);
  cudaGetSymbolAddress((void**)&s.T1a, g_T1a);
  cudaGetSymbolAddress((void**)&s.AZb, g_AZb);
  cudaGetSymbolAddress((void**)&s.T1b, g_T1b);
  cudaGetSymbolAddress((void**)&s.T2 , g_T2 );
  cudaGetSymbolAddress((void**)&s.T3 , g_T3 );
  cudaGetSymbolAddress((void**)&s.Za , g_Za );
  cudaGetSymbolAddress((void**)&s.Zb , g_Zb );
  cudaGetSymbolAddress((void**)&s.A3V, g_A3V);
  cudaGetSymbolAddress((void**)&s.W2 , g_W2 );
  cudaGetSymbolAddress((void**)&s.ATT, g_ATT);

  static Streams st = [](){
    Streams t{};
    cudaStreamCreateWithFlags(&t.stP, cudaStreamNonBlocking);
    cudaEventCreateWithFlags(&t.evF, cudaEventDisableTiming);
    cudaEventCreateWithFlags(&t.evJ, cudaEventDisableTiming);
    cudaEventCreateWithFlags(&t.evC, cudaEventDisableTiming);
    cudaEventCreateWithFlags(&t.evD, cudaEventDisableTiming);
    cudaEventCreateWithFlags(&t.evW0, cudaEventDisableTiming);
    cudaEventCreateWithFlags(&t.evW1, cudaEventDisableTiming);
    return t;
  }();
  static int smset = [](){
    cudaFuncSetAttribute(ppeg_tiled_k, cudaFuncAttributeMaxDynamicSharedMemorySize, 74640);
    cudaFuncSetAttribute(fla3v_k, cudaFuncAttributeMaxDynamicSharedMemorySize, 73728);
    cudaFuncSetAttribute(fattn_k, cudaFuncAttributeMaxDynamicSharedMemorySize, 82944);
    cudaFuncSetAttribute((const void*)hgemm_k<128,128,32,64,true>,
                         cudaFuncAttributeMaxDynamicSharedMemorySize, SMEM_CBIG_TB);
    return (int)cudaFuncSetAttribute((const void*)hgemm_k<64,64,16,32,false>,
                         cudaFuncAttributeMaxDynamicSharedMemorySize, SMEM_C64);
  }();
  (void)smset;

  // Round x + fc1 weight on main; fork layer-weight transposes onto stP
  rc_half4_k<<<(Bb*NIN*Lf/4+255)/256,256>>>(x, s.XR, Bb*NIN*Lf/4);
  cudaEventRecord(st.evW0, 0);
  cudaStreamWaitEvent(st.stP, st.evW0, 0);
  rc_trans_k<<<(Dd*3*Dd+255)/256,256,0,st.stP>>>(l1_qkv, s.WT + W_Q1, Dd, 3*Dd);
  rc_trans_k<<<(Dd*3*Dd+255)/256,256,0,st.stP>>>(l2_qkv, s.WT + W_Q2, Dd, 3*Dd);
  rc_trans_k<<<(Dd*Dd+255)/256,256,0,st.stP>>>(l1_ow, s.WT + W_O1, Dd, Dd);
  rc_trans_k<<<(Dd*Dd+255)/256,256,0,st.stP>>>(l2_ow, s.WT + W_O2, Dd, Dd);
  cudaEventRecord(st.evW1, st.stP);
  rc_trans_k<<<(Lf*Dd+255)/256,256>>>(fc1_w, s.WT + W_FC1, Lf, Dd);

  GP p{};
  // fc1 + relu + token-scatter into H (epi 12)
  p = {s.XR,0,Lf, s.WT+W_FC1,0,Lf, nullptr,0,0, Bb*NIN,Dd,Lf, 1,12, fc1_b,0.f,s.H};
  tg_big(p,1,0);
  cls_k<<<Bb,256>>>(cls_tok, s.H);

  cudaStreamWaitEvent(0, st.evW1, 0);

  attn_layer(s.H, l1_ng, l1_nb, s.WT+W_Q1, s.WT+W_O1, l1_ob, l1_rw, s, st);

  // PPEG: ct half + copyrows on stP (forked), pth half on main
  cudaEventRecord(st.evC, 0);
  cudaStreamWaitEvent(st.stP, st.evC, 0);
  copyrows_k<<<dim3(11,Bb),256,0,st.stP>>>(s.H, s.H2);
  ppeg_tiled_k<<<dim3(1,16,Bb),256,74640,st.stP>>>(s.H, s.H2, 11, 13, 1,
      ct_w7,ct_b7,ct_w5,ct_b5,ct_w3,ct_b3);
  cudaEventRecord(st.evD, st.stP);
  ppeg_tiled_k<<<dim3(25,16,Bb),256,74640>>>(s.H, s.H2, 180, 78, 5,
      pth_w7,pth_b7,pth_w5,pth_b5,pth_w3,pth_b3);
  cudaStreamWaitEvent(0, st.evD, 0);

  attn_layer(s.H2, l2_ng, l2_nb, s.WT+W_Q2, s.WT+W_O2, l2_ob, l2_rw, s, st);

  final_ln_k<<<Bb,256>>>(s.H2, norm_g, norm_b, (float*)d_out);
}